// round 15
// baseline (speedup 1.0000x reference)
#include <cuda_runtime.h>
#include <cuda_fp16.h>
#include <cstdint>

// Problem constants (fixed shapes per reference)
#define NN    50000
#define EE    800000
#define HEADS 12
#define OC    32
#define ICC   128
#define HC    (HEADS * OC)   // 384
#define NEG_SLOPE 0.2f

#define BMM   128            // CTA M tile
#define BNN   64             // B chunk width (= 2 heads)
#define NCHK  (HC / BNN)     // 6 chunks
#define LDA   136            // smem row stride in fp16 elems (128 + 8 pad)
#define NBLK  ((NN + 1023) / 1024)   // 49 scan blocks

// ---------------- scratch (device globals; no allocations allowed) ----------
__device__ __half2 g_h16[(size_t)NN * HC / 2]; // 38.4 MB  h (fp16)
__device__ float   g_asrc[NN * HEADS];
__device__ float   g_adst[NN * HEADS];
__device__ int     g_is64;                     // edge_index dtype flag
__device__ __half  g_wt[HC * ICC];             // W^T fp16, [n][k]
// CSR-by-dst structures
__device__ int g_cnt[NN];        // in-degree (real edges only)
__device__ int g_rowptr[NN];     // exclusive prefix
__device__ int g_cursor[NN];     // fill cursors
__device__ int g_csr[EE];        // src ids grouped by dst
__device__ int g_excl[NN];       // per-block exclusive scan
__device__ int g_bsum[64];       // block sums (padded to 64)

__device__ __forceinline__ void load_edge(const void* __restrict__ ei, int e,
                                          int& src, int& dst) {
    if (g_is64) {
        const long long* p = (const long long*)ei;
        src = (int)p[e];
        dst = (int)p[EE + e];
    } else {
        const int* p = (const int*)ei;
        src = p[e];
        dst = p[EE + e];
    }
}

__device__ __forceinline__ uint32_t smem_u32(const void* p) {
    uint32_t a;
    asm("{ .reg .u64 t; cvta.to.shared.u64 t, %1; cvt.u32.u64 %0, t; }" : "=r"(a) : "l"(p));
    return a;
}

// ---------------- K0: detect dtype + zero degree counters -------------------
__global__ void k_init(const int* __restrict__ ei32) {
    int i = blockIdx.x * blockDim.x + threadIdx.x;
    if (i == 0) {
        bool hi_all_zero = true;
        for (int j = 0; j < 32; j++)
            if (ei32[2 * j + 1] != 0) hi_all_zero = false;
        g_is64 = hi_all_zero ? 1 : 0;
    }
    if (i < NN) g_cnt[i] = 0;
}

// ---------------- K0b: W^T -> fp16, [n][k] layout ---------------------------
__global__ void k_prep(const float* __restrict__ W) {
    int i = blockIdx.x * blockDim.x + threadIdx.x;
    if (i >= HC * ICC) return;
    int n = i / ICC, k = i % ICC;
    g_wt[n * ICC + k] = __float2half(W[k * HC + n]);
}

// ---------------- CSR build (2 edges per thread) ----------------------------
__global__ void k_hist(const void* __restrict__ ei) {
    int e = (blockIdx.x * blockDim.x + threadIdx.x) * 2;
#pragma unroll
    for (int q = 0; q < 2; q++) {
        if (e + q >= EE) return;
        int src, dst;
        load_edge(ei, e + q, src, dst);
        if ((unsigned)dst < NN) atomicAdd(&g_cnt[dst], 1);
    }
}

__global__ void k_scan1() {
    __shared__ int s[1024];
    int tid = threadIdx.x;
    int idx = blockIdx.x * 1024 + tid;
    int v = (idx < NN) ? g_cnt[idx] : 0;
    s[tid] = v;
    __syncthreads();
    for (int off = 1; off < 1024; off <<= 1) {
        int t = (tid >= off) ? s[tid - off] : 0;
        __syncthreads();
        s[tid] += t;
        __syncthreads();
    }
    if (idx < NN) g_excl[idx] = s[tid] - v;
    if (tid == 1023) g_bsum[blockIdx.x] = s[1023];
}

// scan of 49 block sums done locally per block
__global__ void k_scan3() {
    __shared__ int sb[64];
    int tid = threadIdx.x;
    if (tid < 64) sb[tid] = (tid < NBLK) ? g_bsum[tid] : 0;
    __syncthreads();
    if (tid == 0) {
        int run = 0;
#pragma unroll
        for (int i = 0; i < NBLK; i++) { int t = sb[i]; sb[i] = run; run += t; }
    }
    __syncthreads();
    int idx = blockIdx.x * blockDim.x + tid;
    if (idx < NN) {
        int r = g_excl[idx] + sb[idx >> 10];
        g_rowptr[idx] = r;
        g_cursor[idx] = r;
    }
}

__global__ void k_fill(const void* __restrict__ ei) {
    int e = (blockIdx.x * blockDim.x + threadIdx.x) * 2;
#pragma unroll
    for (int q = 0; q < 2; q++) {
        if (e + q >= EE) return;
        int src, dst;
        load_edge(ei, e + q, src, dst);
        if ((unsigned)src < NN && (unsigned)dst < NN) {
            int pos = atomicAdd(&g_cursor[dst], 1);
            g_csr[pos] = src;
        }
    }
}

// ---------------- K1: h = x @ W, A-resident, loop over 6 B chunks -----------
#define SMB_A  0
#define SMB_B  (BMM * LDA * 2)
#define SM_GEMM ((BMM + BNN) * LDA * 2)

__device__ __forceinline__ void ldm_x4(uint32_t addr, uint32_t& r0, uint32_t& r1,
                                       uint32_t& r2, uint32_t& r3) {
    asm volatile("ldmatrix.sync.aligned.m8n8.x4.shared.b16 {%0,%1,%2,%3}, [%4];"
                 : "=r"(r0), "=r"(r1), "=r"(r2), "=r"(r3) : "r"(addr));
}
__device__ __forceinline__ void mma_f16(float* d, uint32_t a0, uint32_t a1,
                                        uint32_t a2, uint32_t a3,
                                        uint32_t b0, uint32_t b1) {
    asm volatile(
        "mma.sync.aligned.m16n8k16.row.col.f32.f16.f16.f32 "
        "{%0,%1,%2,%3}, {%4,%5,%6,%7}, {%8,%9}, {%0,%1,%2,%3};"
        : "+f"(d[0]), "+f"(d[1]), "+f"(d[2]), "+f"(d[3])
        : "r"(a0), "r"(a1), "r"(a2), "r"(a3), "r"(b0), "r"(b1));
}

__global__ void __launch_bounds__(256) k_gemm_mma(const float* __restrict__ x,
                                                  const float* __restrict__ att_src,
                                                  const float* __restrict__ att_dst) {
    extern __shared__ char smem[];
    __half* sA = (__half*)(smem + SMB_A);
    __half* sB = (__half*)(smem + SMB_B);

    const int tid = threadIdx.x;
    const int wid = tid >> 5, lane = tid & 31;
    const int row0 = blockIdx.x * BMM;

    // A tile: 128 rows x 128 fp32 -> fp16, loaded ONCE per CTA
#pragma unroll
    for (int j = 0; j < 16; j++) {
        int s = tid + j * 256;
        int r = s >> 5, c = (s & 31) << 2;
        float4 v = make_float4(0.f, 0.f, 0.f, 0.f);
        int grow = row0 + r;
        if (grow < NN) v = *(const float4*)(x + (size_t)grow * ICC + c);
        __half2 lo = __floats2half2_rn(v.x, v.y);
        __half2 hi = __floats2half2_rn(v.z, v.w);
        uint2 pk;
        pk.x = *(uint32_t*)&lo;
        pk.y = *(uint32_t*)&hi;
        *(uint2*)(sA + r * LDA + c) = pk;
    }

    const uint32_t aB = smem_u32(sA), bB = smem_u32(sB);
    const int warpM = wid * 16;
    const int arow = warpM + (lane & 15);
    const int akoff = (lane >> 4) * 8;
    const int brow = ((lane >> 4) << 3) + (lane & 7);
    const int bkoff = (lane & 8);
    const int r1 = warpM + (lane >> 2);
    const int r2 = r1 + 8;
    const int grow1 = row0 + r1, grow2 = row0 + r2;
    const int cb = (lane & 3) * 2;

    for (int nc = 0; nc < NCHK; nc++) {
        const int n0 = nc * BNN;
#pragma unroll
        for (int j = 0; j < 4; j++) {
            int s = tid + j * 256;
            int r = s >> 4, c = (s & 15) << 3;
            *(uint4*)(sB + r * LDA + c) = *(const uint4*)(g_wt + (n0 + r) * ICC + c);
        }
        __syncthreads();

        float acc[8][4];
#pragma unroll
        for (int nt = 0; nt < 8; nt++)
#pragma unroll
            for (int j = 0; j < 4; j++) acc[nt][j] = 0.f;

#pragma unroll
        for (int kc = 0; kc < 8; kc++) {
            uint32_t a0, a1, a2, a3;
            ldm_x4(aB + (uint32_t)((arow * LDA + kc * 16 + akoff) * 2), a0, a1, a2, a3);
#pragma unroll
            for (int ntp = 0; ntp < 4; ntp++) {
                uint32_t b0, b1, b2, b3;
                ldm_x4(bB + (uint32_t)(((ntp * 16 + brow) * LDA + kc * 16 + bkoff) * 2),
                       b0, b1, b2, b3);
                mma_f16(acc[2 * ntp], a0, a1, a2, a3, b0, b1);
                mma_f16(acc[2 * ntp + 1], a0, a1, a2, a3, b2, b3);
            }
        }

        const int hd0 = nc * 2, hd1 = hd0 + 1;
        float s1h0 = 0.f, d1h0 = 0.f, s2h0 = 0.f, d2h0 = 0.f;
        float s1h1 = 0.f, d1h1 = 0.f, s2h1 = 0.f, d2h1 = 0.f;
#pragma unroll
        for (int nt = 0; nt < 8; nt++) {
            int gcol = n0 + nt * 8 + cb;
            if (grow1 < NN)
                g_h16[(size_t)grow1 * (HC / 2) + (gcol >> 1)] =
                    __floats2half2_rn(acc[nt][0], acc[nt][1]);
            if (grow2 < NN)
                g_h16[(size_t)grow2 * (HC / 2) + (gcol >> 1)] =
                    __floats2half2_rn(acc[nt][2], acc[nt][3]);
            float as0 = __ldg(att_src + gcol), as1 = __ldg(att_src + gcol + 1);
            float ad0 = __ldg(att_dst + gcol), ad1 = __ldg(att_dst + gcol + 1);
            if (nt < 4) {
                s1h0 += acc[nt][0] * as0 + acc[nt][1] * as1;
                d1h0 += acc[nt][0] * ad0 + acc[nt][1] * ad1;
                s2h0 += acc[nt][2] * as0 + acc[nt][3] * as1;
                d2h0 += acc[nt][2] * ad0 + acc[nt][3] * ad1;
            } else {
                s1h1 += acc[nt][0] * as0 + acc[nt][1] * as1;
                d1h1 += acc[nt][0] * ad0 + acc[nt][1] * ad1;
                s2h1 += acc[nt][2] * as0 + acc[nt][3] * as1;
                d2h1 += acc[nt][2] * ad0 + acc[nt][3] * ad1;
            }
        }
#pragma unroll
        for (int o = 1; o <= 2; o <<= 1) {
            s1h0 += __shfl_xor_sync(0xffffffffu, s1h0, o);
            d1h0 += __shfl_xor_sync(0xffffffffu, d1h0, o);
            s2h0 += __shfl_xor_sync(0xffffffffu, s2h0, o);
            d2h0 += __shfl_xor_sync(0xffffffffu, d2h0, o);
            s1h1 += __shfl_xor_sync(0xffffffffu, s1h1, o);
            d1h1 += __shfl_xor_sync(0xffffffffu, d1h1, o);
            s2h1 += __shfl_xor_sync(0xffffffffu, s2h1, o);
            d2h1 += __shfl_xor_sync(0xffffffffu, d2h1, o);
        }
        if ((lane & 3) == 0) {
            if (grow1 < NN) {
                g_asrc[grow1 * HEADS + hd0] = s1h0;
                g_adst[grow1 * HEADS + hd0] = d1h0;
                g_asrc[grow1 * HEADS + hd1] = s1h1;
                g_adst[grow1 * HEADS + hd1] = d1h1;
            }
            if (grow2 < NN) {
                g_asrc[grow2 * HEADS + hd0] = s2h0;
                g_adst[grow2 * HEADS + hd0] = d2h0;
                g_asrc[grow2 * HEADS + hd1] = s2h1;
                g_adst[grow2 * HEADS + hd1] = d2h1;
            }
        }
        __syncthreads();
    }
}

// ---------------- K5: CSR aggregation + fused MLP, warp per dst node -------
// R12 inner loop shape — FROZEN. Block size 512 (halves weight-staging traffic).
__device__ __forceinline__ float leaky(float v) {
    return v > 0.f ? v : NEG_SLOPE * v;
}

__global__ void __launch_bounds__(512) k_aggr(const float* __restrict__ bias,
                                              const float* __restrict__ W1,
                                              const float* __restrict__ b1,
                                              const float* __restrict__ W2,
                                              const float* __restrict__ b2,
                                              float* __restrict__ out) {
    __shared__ float sW1[OC * 2 * OC];   // [c][j] 32x64
    __shared__ float sW2[2 * OC * OC];   // [j][c] 64x32
    __shared__ float sb1[2 * OC], sb2[OC], sbias[OC];
    for (int i = threadIdx.x; i < OC * 2 * OC; i += blockDim.x) {
        sW1[i] = W1[i];
        sW2[i] = W2[i];
    }
    for (int i = threadIdx.x; i < 2 * OC; i += blockDim.x) sb1[i] = b1[i];
    for (int i = threadIdx.x; i < OC; i += blockDim.x) { sb2[i] = b2[i]; sbias[i] = bias[i]; }
    __syncthreads();

    int n = blockIdx.x * (blockDim.x >> 5) + (threadIdx.x >> 5);
    int lane = threadIdx.x & 31;
    if (n >= NN) return;

    const int base = g_rowptr[n];
    const int deg = g_cnt[n];
    const int c = lane & 15, p = lane >> 4;   // channel pair, head parity

    const float adst = (lane < HEADS) ? g_adst[n * HEADS + lane] : 0.f;

    float accx[6], accy[6];
#pragma unroll
    for (int hp = 0; hp < 6; hp++) { accx[hp] = 0.f; accy[hp] = 0.f; }
    float denom;

    {   // self loop
        float ex = (lane < HEADS)
                   ? __expf(leaky(g_asrc[n * HEADS + lane] + adst)) : 0.f;
        denom = ex;
        const __half2* hr = g_h16 + (size_t)n * (HC / 2);
#pragma unroll
        for (int hp = 0; hp < 6; hp++) {
            float a = __shfl_sync(0xffffffffu, ex, hp * 2 + p);
            float2 f = __half22float2(hr[(hp * 2 + p) * 16 + c]);
            accx[hp] += a * f.x;
            accy[hp] += a * f.y;
        }
    }
    for (int i0 = 0; i0 < deg; i0 += 32) {
        int s_i = (i0 + lane < deg) ? g_csr[base + i0 + lane] : 0;
        int cnt = min(32, deg - i0);
        for (int j = 0; j < cnt; j++) {
            int src = __shfl_sync(0xffffffffu, s_i, j);
            float ex = (lane < HEADS)
                       ? __expf(leaky(g_asrc[src * HEADS + lane] + adst)) : 0.f;
            denom += ex;
            const __half2* hr = g_h16 + (size_t)src * (HC / 2);
#pragma unroll
            for (int hp = 0; hp < 6; hp++) {
                float a = __shfl_sync(0xffffffffu, ex, hp * 2 + p);
                float2 f = __half22float2(hr[(hp * 2 + p) * 16 + c]);
                accx[hp] += a * f.x;
                accy[hp] += a * f.y;
            }
        }
    }

    // normalize per head, sum heads -> y channels (2c, 2c+1)
    float resx = 0.f, resy = 0.f;
#pragma unroll
    for (int hp = 0; hp < 6; hp++) {
        float dh = __shfl_sync(0xffffffffu, denom, hp * 2 + p) + 1e-16f;
        float rinv = __frcp_rn(dh);
        resx += accx[hp] * rinv;
        resy += accy[hp] * rinv;
    }
    resx += __shfl_xor_sync(0xffffffffu, resx, 16);   // all lanes now hold y
    resy += __shfl_xor_sync(0xffffffffu, resy, 16);

    // ---- fused MLP: y -> relu -> W1 -> relu -> W2 -> +y -> relu ----
    const float inv = 1.0f / (float)HEADS;
    float yrx = resx * inv + sbias[2 * c];
    float yry = resy * inv + sbias[2 * c + 1];
    yrx = yrx > 0.f ? yrx : 0.f;
    yry = yry > 0.f ? yry : 0.f;

    float t0 = sb1[2 * lane], t1 = sb1[2 * lane + 1];
#pragma unroll
    for (int k = 0; k < 16; k++) {
        float ykx = __shfl_sync(0xffffffffu, yrx, k);
        float yky = __shfl_sync(0xffffffffu, yry, k);
        t0 += ykx * sW1[(2 * k) * 64 + 2 * lane]     + yky * sW1[(2 * k + 1) * 64 + 2 * lane];
        t1 += ykx * sW1[(2 * k) * 64 + 2 * lane + 1] + yky * sW1[(2 * k + 1) * 64 + 2 * lane + 1];
    }
    t0 = t0 > 0.f ? t0 : 0.f;
    t1 = t1 > 0.f ? t1 : 0.f;

    float z0 = sb2[2 * c], z1 = sb2[2 * c + 1];
#pragma unroll
    for (int k = 0; k < 32; k++) {
        float tt0 = __shfl_sync(0xffffffffu, t0, k);
        float tt1 = __shfl_sync(0xffffffffu, t1, k);
        z0 += tt0 * sW2[(2 * k) * OC + 2 * c]     + tt1 * sW2[(2 * k + 1) * OC + 2 * c];
        z1 += tt0 * sW2[(2 * k) * OC + 2 * c + 1] + tt1 * sW2[(2 * k + 1) * OC + 2 * c + 1];
    }
    if (p == 0) {
        float o0 = yrx + z0, o1 = yry + z1;
        o0 = o0 > 0.f ? o0 : 0.f;
        o1 = o1 > 0.f ? o1 : 0.f;
        *(float2*)(out + n * OC + 2 * c) = make_float2(o0, o1);
    }
}

// ---------------- launch -----------------------------------------------------
extern "C" void kernel_launch(void* const* d_in, const int* in_sizes, int n_in,
                              void* d_out, int out_size) {
    const float* x       = (const float*)d_in[0];
    const void*  ei      = d_in[1];
    const float* W       = (const float*)d_in[2];
    const float* att_src = (const float*)d_in[3];
    const float* att_dst = (const float*)d_in[4];
    const float* bias    = (const float*)d_in[5];
    const float* W1      = (const float*)d_in[6];
    const float* b1      = (const float*)d_in[7];
    const float* W2      = (const float*)d_in[8];
    const float* b2      = (const float*)d_in[9];
    float*       out     = (float*)d_out;

    static cudaStream_t sB = nullptr;
    static cudaEvent_t evFork = nullptr, evJoin = nullptr;
    static bool init_done = false;
    if (!init_done) {
        cudaFuncSetAttribute(k_gemm_mma, cudaFuncAttributeMaxDynamicSharedMemorySize,
                             SM_GEMM);
        cudaStreamCreateWithFlags(&sB, cudaStreamNonBlocking);
        cudaEventCreateWithFlags(&evFork, cudaEventDisableTiming);
        cudaEventCreateWithFlags(&evJoin, cudaEventDisableTiming);
        init_done = true;
    }

    // fork: side stream B runs the GEMM chain (independent of edge_index)
    cudaEventRecord(evFork, 0);
    cudaStreamWaitEvent(sB, evFork, 0);

    // stream B: W prep + fused GEMM/attention-logits (A-resident, x read once)
    k_prep<<<(HC * ICC + 255) / 256, 256, 0, sB>>>(W);
    k_gemm_mma<<<(NN + BMM - 1) / BMM, 256, SM_GEMM, sB>>>(x, att_src, att_dst);
    cudaEventRecord(evJoin, sB);

    // main stream: CSR build (edge_index only), 2 edges/thread
    k_init<<<(NN + 255) / 256, 256>>>((const int*)ei);
    k_hist<<<(EE / 2 + 255) / 256, 256>>>(ei);
    k_scan1<<<NBLK, 1024>>>();
    k_scan3<<<(NN + 255) / 256, 256>>>();
    k_fill<<<(EE / 2 + 255) / 256, 256>>>(ei);

    // join: aggregation needs both chains
    cudaStreamWaitEvent(0, evJoin, 0);
    k_aggr<<<(NN + 15) / 16, 512>>>(bias, W1, b1, W2, b2, out);
}

// round 16
// speedup vs baseline: 1.3422x; 1.3422x over previous
#include <cuda_runtime.h>
#include <cuda_fp16.h>
#include <cstdint>

// Problem constants (fixed shapes per reference)
#define NN    50000
#define EE    800000
#define HEADS 12
#define OC    32
#define ICC   128
#define HC    (HEADS * OC)   // 384
#define NEG_SLOPE 0.2f

#define BMM   128            // CTA M tile
#define BNN   64             // B chunk width (= 2 heads)
#define NCHK  (HC / BNN)     // 6 chunks
#define LDA   136            // smem row stride in fp16 elems (128 + 8 pad)
#define NBLK  ((NN + 1023) / 1024)   // 49 scan blocks

// ---------------- scratch (device globals; no allocations allowed) ----------
__device__ __half2 g_h16[(size_t)NN * HC / 2]; // 38.4 MB  h (fp16)
__device__ float   g_asrc[NN * HEADS];
__device__ float   g_adst[NN * HEADS];
__device__ int     g_is64;                     // edge_index dtype flag
__device__ __half  g_wt[HC * ICC];             // W^T fp16, [n][k]
// CSR-by-dst structures
__device__ int g_cnt[NN];        // in-degree (real edges only)
__device__ int g_rowptr[NN];     // exclusive prefix
__device__ int g_cursor[NN];     // fill cursors
__device__ int g_csr[EE];        // src ids grouped by dst
__device__ int g_excl[NN];       // per-block exclusive scan
__device__ int g_bsum[64];       // block sums (padded to 64)

__device__ __forceinline__ void load_edge(const void* __restrict__ ei, int e,
                                          int& src, int& dst) {
    if (g_is64) {
        const long long* p = (const long long*)ei;
        src = (int)p[e];
        dst = (int)p[EE + e];
    } else {
        const int* p = (const int*)ei;
        src = p[e];
        dst = p[EE + e];
    }
}

__device__ __forceinline__ uint32_t smem_u32(const void* p) {
    uint32_t a;
    asm("{ .reg .u64 t; cvta.to.shared.u64 t, %1; cvt.u32.u64 %0, t; }" : "=r"(a) : "l"(p));
    return a;
}

// ---------------- K0: detect dtype + zero degree counters -------------------
__global__ void k_init(const int* __restrict__ ei32) {
    int i = blockIdx.x * blockDim.x + threadIdx.x;
    if (i == 0) {
        bool hi_all_zero = true;
        for (int j = 0; j < 32; j++)
            if (ei32[2 * j + 1] != 0) hi_all_zero = false;
        g_is64 = hi_all_zero ? 1 : 0;
    }
    if (i < NN) g_cnt[i] = 0;
}

// ---------------- K0b: W^T -> fp16, [n][k] layout ---------------------------
__global__ void k_prep(const float* __restrict__ W) {
    int i = blockIdx.x * blockDim.x + threadIdx.x;
    if (i >= HC * ICC) return;
    int n = i / ICC, k = i % ICC;
    g_wt[n * ICC + k] = __float2half(W[k * HC + n]);
}

// ---------------- CSR build --------------------------------------------------
__global__ void k_hist(const void* __restrict__ ei) {
    int e = blockIdx.x * blockDim.x + threadIdx.x;
    if (e >= EE) return;
    int src, dst;
    load_edge(ei, e, src, dst);
    if ((unsigned)dst < NN) atomicAdd(&g_cnt[dst], 1);
}

__global__ void k_scan1() {
    __shared__ int s[1024];
    int tid = threadIdx.x;
    int idx = blockIdx.x * 1024 + tid;
    int v = (idx < NN) ? g_cnt[idx] : 0;
    s[tid] = v;
    __syncthreads();
    for (int off = 1; off < 1024; off <<= 1) {
        int t = (tid >= off) ? s[tid - off] : 0;
        __syncthreads();
        s[tid] += t;
        __syncthreads();
    }
    if (idx < NN) g_excl[idx] = s[tid] - v;
    if (tid == 1023) g_bsum[blockIdx.x] = s[1023];
}

// scan of 49 block sums done locally per block
__global__ void k_scan3() {
    __shared__ int sb[64];
    int tid = threadIdx.x;
    if (tid < 64) sb[tid] = (tid < NBLK) ? g_bsum[tid] : 0;
    __syncthreads();
    if (tid == 0) {
        int run = 0;
#pragma unroll
        for (int i = 0; i < NBLK; i++) { int t = sb[i]; sb[i] = run; run += t; }
    }
    __syncthreads();
    int idx = blockIdx.x * blockDim.x + tid;
    if (idx < NN) {
        int r = g_excl[idx] + sb[idx >> 10];
        g_rowptr[idx] = r;
        g_cursor[idx] = r;
    }
}

__global__ void k_fill(const void* __restrict__ ei) {
    int e = blockIdx.x * blockDim.x + threadIdx.x;
    if (e >= EE) return;
    int src, dst;
    load_edge(ei, e, src, dst);
    if ((unsigned)src >= NN || (unsigned)dst >= NN) return;
    int pos = atomicAdd(&g_cursor[dst], 1);
    g_csr[pos] = src;
}

// ---------------- K1: h = x @ W, A-resident, loop over 6 B chunks -----------
#define SMB_A  0
#define SMB_B  (BMM * LDA * 2)
#define SM_GEMM ((BMM + BNN) * LDA * 2)

__device__ __forceinline__ void ldm_x4(uint32_t addr, uint32_t& r0, uint32_t& r1,
                                       uint32_t& r2, uint32_t& r3) {
    asm volatile("ldmatrix.sync.aligned.m8n8.x4.shared.b16 {%0,%1,%2,%3}, [%4];"
                 : "=r"(r0), "=r"(r1), "=r"(r2), "=r"(r3) : "r"(addr));
}
__device__ __forceinline__ void mma_f16(float* d, uint32_t a0, uint32_t a1,
                                        uint32_t a2, uint32_t a3,
                                        uint32_t b0, uint32_t b1) {
    asm volatile(
        "mma.sync.aligned.m16n8k16.row.col.f32.f16.f16.f32 "
        "{%0,%1,%2,%3}, {%4,%5,%6,%7}, {%8,%9}, {%0,%1,%2,%3};"
        : "+f"(d[0]), "+f"(d[1]), "+f"(d[2]), "+f"(d[3])
        : "r"(a0), "r"(a1), "r"(a2), "r"(a3), "r"(b0), "r"(b1));
}

__global__ void __launch_bounds__(256) k_gemm_mma(const float* __restrict__ x,
                                                  const float* __restrict__ att_src,
                                                  const float* __restrict__ att_dst) {
    extern __shared__ char smem[];
    __half* sA = (__half*)(smem + SMB_A);
    __half* sB = (__half*)(smem + SMB_B);

    const int tid = threadIdx.x;
    const int wid = tid >> 5, lane = tid & 31;
    const int row0 = blockIdx.x * BMM;

    // A tile: 128 rows x 128 fp32 -> fp16, loaded ONCE per CTA
#pragma unroll
    for (int j = 0; j < 16; j++) {
        int s = tid + j * 256;
        int r = s >> 5, c = (s & 31) << 2;
        float4 v = make_float4(0.f, 0.f, 0.f, 0.f);
        int grow = row0 + r;
        if (grow < NN) v = *(const float4*)(x + (size_t)grow * ICC + c);
        __half2 lo = __floats2half2_rn(v.x, v.y);
        __half2 hi = __floats2half2_rn(v.z, v.w);
        uint2 pk;
        pk.x = *(uint32_t*)&lo;
        pk.y = *(uint32_t*)&hi;
        *(uint2*)(sA + r * LDA + c) = pk;
    }

    const uint32_t aB = smem_u32(sA), bB = smem_u32(sB);
    const int warpM = wid * 16;
    const int arow = warpM + (lane & 15);
    const int akoff = (lane >> 4) * 8;
    const int brow = ((lane >> 4) << 3) + (lane & 7);
    const int bkoff = (lane & 8);
    const int r1 = warpM + (lane >> 2);
    const int r2 = r1 + 8;
    const int grow1 = row0 + r1, grow2 = row0 + r2;
    const int cb = (lane & 3) * 2;

    for (int nc = 0; nc < NCHK; nc++) {
        const int n0 = nc * BNN;
#pragma unroll
        for (int j = 0; j < 4; j++) {
            int s = tid + j * 256;
            int r = s >> 4, c = (s & 15) << 3;
            *(uint4*)(sB + r * LDA + c) = *(const uint4*)(g_wt + (n0 + r) * ICC + c);
        }
        __syncthreads();

        float acc[8][4];
#pragma unroll
        for (int nt = 0; nt < 8; nt++)
#pragma unroll
            for (int j = 0; j < 4; j++) acc[nt][j] = 0.f;

#pragma unroll
        for (int kc = 0; kc < 8; kc++) {
            uint32_t a0, a1, a2, a3;
            ldm_x4(aB + (uint32_t)((arow * LDA + kc * 16 + akoff) * 2), a0, a1, a2, a3);
#pragma unroll
            for (int ntp = 0; ntp < 4; ntp++) {
                uint32_t b0, b1, b2, b3;
                ldm_x4(bB + (uint32_t)(((ntp * 16 + brow) * LDA + kc * 16 + bkoff) * 2),
                       b0, b1, b2, b3);
                mma_f16(acc[2 * ntp], a0, a1, a2, a3, b0, b1);
                mma_f16(acc[2 * ntp + 1], a0, a1, a2, a3, b2, b3);
            }
        }

        const int hd0 = nc * 2, hd1 = hd0 + 1;
        float s1h0 = 0.f, d1h0 = 0.f, s2h0 = 0.f, d2h0 = 0.f;
        float s1h1 = 0.f, d1h1 = 0.f, s2h1 = 0.f, d2h1 = 0.f;
#pragma unroll
        for (int nt = 0; nt < 8; nt++) {
            int gcol = n0 + nt * 8 + cb;
            if (grow1 < NN)
                g_h16[(size_t)grow1 * (HC / 2) + (gcol >> 1)] =
                    __floats2half2_rn(acc[nt][0], acc[nt][1]);
            if (grow2 < NN)
                g_h16[(size_t)grow2 * (HC / 2) + (gcol >> 1)] =
                    __floats2half2_rn(acc[nt][2], acc[nt][3]);
            float as0 = __ldg(att_src + gcol), as1 = __ldg(att_src + gcol + 1);
            float ad0 = __ldg(att_dst + gcol), ad1 = __ldg(att_dst + gcol + 1);
            if (nt < 4) {
                s1h0 += acc[nt][0] * as0 + acc[nt][1] * as1;
                d1h0 += acc[nt][0] * ad0 + acc[nt][1] * ad1;
                s2h0 += acc[nt][2] * as0 + acc[nt][3] * as1;
                d2h0 += acc[nt][2] * ad0 + acc[nt][3] * ad1;
            } else {
                s1h1 += acc[nt][0] * as0 + acc[nt][1] * as1;
                d1h1 += acc[nt][0] * ad0 + acc[nt][1] * ad1;
                s2h1 += acc[nt][2] * as0 + acc[nt][3] * as1;
                d2h1 += acc[nt][2] * ad0 + acc[nt][3] * ad1;
            }
        }
#pragma unroll
        for (int o = 1; o <= 2; o <<= 1) {
            s1h0 += __shfl_xor_sync(0xffffffffu, s1h0, o);
            d1h0 += __shfl_xor_sync(0xffffffffu, d1h0, o);
            s2h0 += __shfl_xor_sync(0xffffffffu, s2h0, o);
            d2h0 += __shfl_xor_sync(0xffffffffu, d2h0, o);
            s1h1 += __shfl_xor_sync(0xffffffffu, s1h1, o);
            d1h1 += __shfl_xor_sync(0xffffffffu, d1h1, o);
            s2h1 += __shfl_xor_sync(0xffffffffu, s2h1, o);
            d2h1 += __shfl_xor_sync(0xffffffffu, d2h1, o);
        }
        if ((lane & 3) == 0) {
            if (grow1 < NN) {
                g_asrc[grow1 * HEADS + hd0] = s1h0;
                g_adst[grow1 * HEADS + hd0] = d1h0;
                g_asrc[grow1 * HEADS + hd1] = s1h1;
                g_adst[grow1 * HEADS + hd1] = d1h1;
            }
            if (grow2 < NN) {
                g_asrc[grow2 * HEADS + hd0] = s2h0;
                g_adst[grow2 * HEADS + hd0] = d2h0;
                g_asrc[grow2 * HEADS + hd1] = s2h1;
                g_adst[grow2 * HEADS + hd1] = d2h1;
            }
        }
        __syncthreads();
    }
}

// ---------------- K5: CSR aggregation + fused MLP, warp per dst node -------
// FROZEN: R12 loop shape, 256 threads / 8 warps per block.
__device__ __forceinline__ float leaky(float v) {
    return v > 0.f ? v : NEG_SLOPE * v;
}

__global__ void __launch_bounds__(256) k_aggr(const float* __restrict__ bias,
                                              const float* __restrict__ W1,
                                              const float* __restrict__ b1,
                                              const float* __restrict__ W2,
                                              const float* __restrict__ b2,
                                              float* __restrict__ out) {
    __shared__ float sW1[OC * 2 * OC];   // [c][j] 32x64
    __shared__ float sW2[2 * OC * OC];   // [j][c] 64x32
    __shared__ float sb1[2 * OC], sb2[OC], sbias[OC];
    for (int i = threadIdx.x; i < OC * 2 * OC; i += blockDim.x) {
        sW1[i] = W1[i];
        sW2[i] = W2[i];
    }
    for (int i = threadIdx.x; i < 2 * OC; i += blockDim.x) sb1[i] = b1[i];
    for (int i = threadIdx.x; i < OC; i += blockDim.x) { sb2[i] = b2[i]; sbias[i] = bias[i]; }
    __syncthreads();

    int n = blockIdx.x * (blockDim.x >> 5) + (threadIdx.x >> 5);
    int lane = threadIdx.x & 31;
    if (n >= NN) return;

    const int base = g_rowptr[n];
    const int deg = g_cnt[n];
    const int c = lane & 15, p = lane >> 4;   // channel pair, head parity

    const float adst = (lane < HEADS) ? g_adst[n * HEADS + lane] : 0.f;

    float accx[6], accy[6];
#pragma unroll
    for (int hp = 0; hp < 6; hp++) { accx[hp] = 0.f; accy[hp] = 0.f; }
    float denom;

    {   // self loop
        float ex = (lane < HEADS)
                   ? __expf(leaky(g_asrc[n * HEADS + lane] + adst)) : 0.f;
        denom = ex;
        const __half2* hr = g_h16 + (size_t)n * (HC / 2);
#pragma unroll
        for (int hp = 0; hp < 6; hp++) {
            float a = __shfl_sync(0xffffffffu, ex, hp * 2 + p);
            float2 f = __half22float2(hr[(hp * 2 + p) * 16 + c]);
            accx[hp] += a * f.x;
            accy[hp] += a * f.y;
        }
    }
    for (int i0 = 0; i0 < deg; i0 += 32) {
        int s_i = (i0 + lane < deg) ? g_csr[base + i0 + lane] : 0;
        int cnt = min(32, deg - i0);
        for (int j = 0; j < cnt; j++) {
            int src = __shfl_sync(0xffffffffu, s_i, j);
            float ex = (lane < HEADS)
                       ? __expf(leaky(g_asrc[src * HEADS + lane] + adst)) : 0.f;
            denom += ex;
            const __half2* hr = g_h16 + (size_t)src * (HC / 2);
#pragma unroll
            for (int hp = 0; hp < 6; hp++) {
                float a = __shfl_sync(0xffffffffu, ex, hp * 2 + p);
                float2 f = __half22float2(hr[(hp * 2 + p) * 16 + c]);
                accx[hp] += a * f.x;
                accy[hp] += a * f.y;
            }
        }
    }

    // normalize per head, sum heads -> y channels (2c, 2c+1)
    float resx = 0.f, resy = 0.f;
#pragma unroll
    for (int hp = 0; hp < 6; hp++) {
        float dh = __shfl_sync(0xffffffffu, denom, hp * 2 + p) + 1e-16f;
        float rinv = __frcp_rn(dh);
        resx += accx[hp] * rinv;
        resy += accy[hp] * rinv;
    }
    resx += __shfl_xor_sync(0xffffffffu, resx, 16);   // all lanes now hold y
    resy += __shfl_xor_sync(0xffffffffu, resy, 16);

    // ---- fused MLP: y -> relu -> W1 -> relu -> W2 -> +y -> relu ----
    const float inv = 1.0f / (float)HEADS;
    float yrx = resx * inv + sbias[2 * c];
    float yry = resy * inv + sbias[2 * c + 1];
    yrx = yrx > 0.f ? yrx : 0.f;
    yry = yry > 0.f ? yry : 0.f;

    float t0 = sb1[2 * lane], t1 = sb1[2 * lane + 1];
#pragma unroll
    for (int k = 0; k < 16; k++) {
        float ykx = __shfl_sync(0xffffffffu, yrx, k);
        float yky = __shfl_sync(0xffffffffu, yry, k);
        t0 += ykx * sW1[(2 * k) * 64 + 2 * lane]     + yky * sW1[(2 * k + 1) * 64 + 2 * lane];
        t1 += ykx * sW1[(2 * k) * 64 + 2 * lane + 1] + yky * sW1[(2 * k + 1) * 64 + 2 * lane + 1];
    }
    t0 = t0 > 0.f ? t0 : 0.f;
    t1 = t1 > 0.f ? t1 : 0.f;

    float z0 = sb2[2 * c], z1 = sb2[2 * c + 1];
#pragma unroll
    for (int k = 0; k < 32; k++) {
        float tt0 = __shfl_sync(0xffffffffu, t0, k);
        float tt1 = __shfl_sync(0xffffffffu, t1, k);
        z0 += tt0 * sW2[(2 * k) * OC + 2 * c]     + tt1 * sW2[(2 * k + 1) * OC + 2 * c];
        z1 += tt0 * sW2[(2 * k) * OC + 2 * c + 1] + tt1 * sW2[(2 * k + 1) * OC + 2 * c + 1];
    }
    if (p == 0) {
        float o0 = yrx + z0, o1 = yry + z1;
        o0 = o0 > 0.f ? o0 : 0.f;
        o1 = o1 > 0.f ? o1 : 0.f;
        *(float2*)(out + n * OC + 2 * c) = make_float2(o0, o1);
    }
}

// ---------------- launch -----------------------------------------------------
extern "C" void kernel_launch(void* const* d_in, const int* in_sizes, int n_in,
                              void* d_out, int out_size) {
    const float* x       = (const float*)d_in[0];
    const void*  ei      = d_in[1];
    const float* W       = (const float*)d_in[2];
    const float* att_src = (const float*)d_in[3];
    const float* att_dst = (const float*)d_in[4];
    const float* bias    = (const float*)d_in[5];
    const float* W1      = (const float*)d_in[6];
    const float* b1      = (const float*)d_in[7];
    const float* W2      = (const float*)d_in[8];
    const float* b2      = (const float*)d_in[9];
    float*       out     = (float*)d_out;

    static cudaStream_t sB = nullptr;
    static cudaEvent_t evFork = nullptr, evJoin = nullptr;
    static bool init_done = false;
    if (!init_done) {
        cudaFuncSetAttribute(k_gemm_mma, cudaFuncAttributeMaxDynamicSharedMemorySize,
                             SM_GEMM);
        cudaStreamCreateWithFlags(&sB, cudaStreamNonBlocking);
        cudaEventCreateWithFlags(&evFork, cudaEventDisableTiming);
        cudaEventCreateWithFlags(&evJoin, cudaEventDisableTiming);
        init_done = true;
    }

    // fork: side stream B runs the GEMM chain (independent of edge_index)
    cudaEventRecord(evFork, 0);
    cudaStreamWaitEvent(sB, evFork, 0);

    // stream B: W prep + fused GEMM/attention-logits (A-resident, x read once)
    k_prep<<<(HC * ICC + 255) / 256, 256, 0, sB>>>(W);
    k_gemm_mma<<<(NN + BMM - 1) / BMM, 256, SM_GEMM, sB>>>(x, att_src, att_dst);
    cudaEventRecord(evJoin, sB);

    // main stream: CSR build (edge_index only)
    k_init<<<(NN + 255) / 256, 256>>>((const int*)ei);
    k_hist<<<(EE + 255) / 256, 256>>>(ei);
    k_scan1<<<NBLK, 1024>>>();
    k_scan3<<<(NN + 255) / 256, 256>>>();
    k_fill<<<(EE + 255) / 256, 256>>>(ei);

    // join: aggregation needs both chains
    cudaStreamWaitEvent(0, evJoin, 0);
    k_aggr<<<(NN + 7) / 8, 256>>>(bias, W1, b1, W2, b2, out);
}